// round 2
// baseline (speedup 1.0000x reference)
#include <cuda_runtime.h>
#include <cstdint>

#define B_    64
#define S_    1024
#define CIN   5
#define KS    4
#define H1    64
#define H2    16
#define OUTC  32
#define L1    1021          // S-K+1
#define C1    22            // H2+CIN+1
#define SIGC1 506
#define SC1P  512           // padded
#define L2    1018
#define SIGC2 272
#define NC1   16            // chunks for sig1 scan
#define CH1   64            // chunk length
#define PAD   68            // smem row stride (floats): 16B-aligned, bank-shifted

// ---- scratch (device globals; no runtime allocation) ----
__device__ float g_h[B_ * L1 * C1];                      // ~5.7 MB
__device__ float g_s1[(size_t)B_ * L1 * SC1P];           // ~134 MB
__device__ float g_wpad[KS * SC1P * H1];                 // 512 KB
__device__ float g_csum[B_ * NC1 * SC1P];                // 2 MB
__device__ float g_h2[B_ * L2 * H2];                     // ~4.2 MB

// ============================================================
// Repack a2_w0 (O,C,K) -> wpad[k][c_pad][o], zero pad c>=506
// ============================================================
__global__ void k_repack(const float* __restrict__ w0) {
    int idx = blockIdx.x * blockDim.x + threadIdx.x;     // 0..131071
    int o  = idx & 63;
    int c  = (idx >> 6) & (SC1P - 1);
    int kk = idx >> 15;
    float v = 0.f;
    if (c < SIGC1) v = w0[(o * SIGC1 + c) * KS + kk];
    g_wpad[idx] = v;
}

// ============================================================
// Augment 1: x (B,S,5) -> h (B,L1,22) = [x_trunc(5), time(1), conv(16)]
// ============================================================
__global__ __launch_bounds__(128) void k_aug1(
    const float* __restrict__ x,
    const float* __restrict__ w0, const float* __restrict__ b0,
    const float* __restrict__ w1, const float* __restrict__ b1,
    const float* __restrict__ w2, const float* __restrict__ b2)
{
    __shared__ float w0s[H1*CIN*KS], w1s[H1*H1], w2s[H2*H1];
    __shared__ float b0s[H1], b1s[H1], b2s[H2];
    int tid = threadIdx.x;
    for (int i = tid; i < H1*CIN*KS; i += 128) w0s[i] = w0[i];
    for (int i = tid; i < H1*H1;     i += 128) w1s[i] = w1[i];
    for (int i = tid; i < H2*H1;     i += 128) w2s[i] = w2[i];
    if (tid < H1) { b0s[tid] = b0[tid]; b1s[tid] = b1[tid]; }
    if (tid < H2) b2s[tid] = b2[tid];
    __syncthreads();

    int b = blockIdx.y;
    int t = blockIdx.x * 128 + tid;
    if (t >= L1) return;

    float xr[KS][CIN];
#pragma unroll
    for (int k = 0; k < KS; k++)
#pragma unroll
        for (int c = 0; c < CIN; c++)
            xr[k][c] = x[((size_t)(b * S_) + t + k) * CIN + c];

    float z1[H1];
#pragma unroll
    for (int o = 0; o < H1; o++) {
        float s = b0s[o];
#pragma unroll
        for (int c = 0; c < CIN; c++)
#pragma unroll
            for (int k = 0; k < KS; k++)
                s += w0s[(o*CIN + c)*KS + k] * xr[k][c];
        z1[o] = fmaxf(s, 0.f);
    }
    float z3[H2];
#pragma unroll
    for (int o = 0; o < H2; o++) z3[o] = b2s[o];
    for (int o2 = 0; o2 < H1; o2++) {
        float s = b1s[o2];
#pragma unroll
        for (int c = 0; c < H1; c++) s += w1s[o2*H1 + c] * z1[c];
        s = fmaxf(s, 0.f);
#pragma unroll
        for (int o = 0; o < H2; o++) z3[o] += w2s[o*H1 + o2] * s;
    }
    float* hrow = &g_h[(size_t)(b * L1 + t) * C1];
#pragma unroll
    for (int c = 0; c < CIN; c++) hrow[c] = xr[KS-1][c];
    hrow[CIN] = (float)t * (1.0f / (float)(L1 - 1));
#pragma unroll
    for (int o = 0; o < H2; o++) hrow[CIN + 1 + o] = z3[o];
}

// ============================================================
// Sig1 pass A: per-(b,chunk) sums of level-2 increments
// inc[t](i,j) = h[t-1][i]*dx[j] + 0.5*dx[i]*dx[j],  dx = h[t]-h[t-1], h[-1]=0
// ============================================================
__global__ __launch_bounds__(512) void k_sig1_sum() {
    __shared__ float hs[CH1 + 1][C1];
    int b = blockIdx.y, nc = blockIdx.x, tid = threadIdx.x;
    int c0 = nc * CH1;
    for (int idx = tid; idx < (CH1 + 1) * C1; idx += 512) {
        int r = idx / C1, c = idx - r * C1;
        int row = c0 - 1 + r;
        hs[r][c] = (row >= 0 && row < L1) ? g_h[(size_t)(b * L1 + row) * C1 + c] : 0.f;
    }
    __syncthreads();
    if (tid >= C1 * C1) return;
    int i = tid / C1, j = tid - i * C1;
    float acc = 0.f;
    int tend = min(c0 + CH1, L1);
    for (int t = c0; t < tend; t++) {
        int r = t - c0 + 1;
        float hpi = hs[r-1][i], hpj = hs[r-1][j];
        float dxi = hs[r][i] - hpi, dxj = hs[r][j] - hpj;
        acc += hpi * dxj + 0.5f * dxi * dxj;
    }
    g_csum[(b * NC1 + nc) * SC1P + tid] = acc;
}

// Sig1 pass B: exclusive prefix of chunk sums (in place)
__global__ void k_sig1_prefix() {
    int b = blockIdx.x, tid = threadIdx.x;
    if (tid >= C1 * C1) return;
    float run = 0.f;
    for (int nc = 0; nc < NC1; nc++) {
        int idx = (b * NC1 + nc) * SC1P + tid;
        float v = g_csum[idx];
        g_csum[idx] = run;
        run += v;
    }
}

// Sig1 pass C: rescan chunk from offset, write s1 = [h(22) | S2(484) | pad(6)]
__global__ __launch_bounds__(512) void k_sig1_write() {
    __shared__ float hs[CH1 + 1][C1];
    int b = blockIdx.y, nc = blockIdx.x, tid = threadIdx.x;
    int c0 = nc * CH1;
    for (int idx = tid; idx < (CH1 + 1) * C1; idx += 512) {
        int r = idx / C1, c = idx - r * C1;
        int row = c0 - 1 + r;
        hs[r][c] = (row >= 0 && row < L1) ? g_h[(size_t)(b * L1 + row) * C1 + c] : 0.f;
    }
    __syncthreads();
    int tend = min(c0 + CH1, L1);
    if (tid < C1 * C1) {
        int i = tid / C1, j = tid - i * C1;
        float acc = g_csum[(b * NC1 + nc) * SC1P + tid];
        for (int t = c0; t < tend; t++) {
            int r = t - c0 + 1;
            float hpi = hs[r-1][i], hpj = hs[r-1][j];
            float dxi = hs[r][i] - hpi, dxj = hs[r][j] - hpj;
            acc += hpi * dxj + 0.5f * dxi * dxj;
            g_s1[((size_t)(b * L1 + t)) * SC1P + C1 + tid] = acc;
        }
    } else {
        int c = tid - C1 * C1;       // 0..27
        int ch = (c < C1) ? c : (C1 * C1 + c);   // 0..21 or 506..511
        for (int t = c0; t < tend; t++) {
            int r = t - c0 + 1;
            float v = (c < C1) ? hs[r][c] : 0.f;
            g_s1[((size_t)(b * L1 + t)) * SC1P + ch] = v;
        }
    }
}

// ============================================================
// Conv stack 2 as tiled GEMM + fused 1x1 epilogue -> h2 (B,L2,16)
// y0[t][o] = sum_{kk,c} wpad[kk][c][o] * s1[t+kk][c]
// ============================================================
__global__ __launch_bounds__(256) void k_conv2(
    const float* __restrict__ b0,
    const float* __restrict__ w1, const float* __restrict__ b1,
    const float* __restrict__ w2, const float* __restrict__ b2)
{
    __shared__ union {
        struct { float As[64][PAD]; float Bs[64][64]; } g;
        struct { float Z[64][PAD];  float W[64][PAD]; } e;
    } sm;
    __shared__ float b0s[64], b1s[64], b2s[16];
    int tid = threadIdx.x;
    int b = blockIdx.y, t0 = blockIdx.x * 64;
    if (tid < 64) { b0s[tid] = b0[tid]; b1s[tid] = b1[tid]; }
    if (tid < 16) b2s[tid] = b2[tid];

    int tx = tid & 15, ty = tid >> 4;
    int m0 = ty * 4, n0 = tx * 4;
    float acc[4][4] = {};

    const float* pAbase = g_s1 + (size_t)b * L1 * SC1P;
    for (int kb = 0; kb < 32; kb++) {
        int kk = kb >> 3;
        int cb = (kb & 7) << 6;
#pragma unroll
        for (int q = 0; q < 4; q++) {
            int idx = tid + q * 256;
            int m = idx >> 4, c4 = idx & 15;
            int row = t0 + kk + m;
            float4 v = make_float4(0.f, 0.f, 0.f, 0.f);
            if (row < L1)
                v = *(const float4*)&pAbase[(size_t)row * SC1P + cb + c4 * 4];
            sm.g.As[c4*4+0][m] = v.x; sm.g.As[c4*4+1][m] = v.y;
            sm.g.As[c4*4+2][m] = v.z; sm.g.As[c4*4+3][m] = v.w;
        }
        const float4* pB = (const float4*)(g_wpad + (kk * SC1P + cb) * 64);
#pragma unroll
        for (int q = 0; q < 4; q++)
            ((float4*)&sm.g.Bs[0][0])[tid + q * 256] = pB[tid + q * 256];
        __syncthreads();
#pragma unroll
        for (int k = 0; k < 64; k++) {
            float4 a = *(const float4*)&sm.g.As[k][m0];
            float4 w = *(const float4*)&sm.g.Bs[k][n0];
            acc[0][0] += a.x*w.x; acc[0][1] += a.x*w.y; acc[0][2] += a.x*w.z; acc[0][3] += a.x*w.w;
            acc[1][0] += a.y*w.x; acc[1][1] += a.y*w.y; acc[1][2] += a.y*w.z; acc[1][3] += a.y*w.w;
            acc[2][0] += a.z*w.x; acc[2][1] += a.z*w.y; acc[2][2] += a.z*w.z; acc[2][3] += a.z*w.w;
            acc[3][0] += a.w*w.x; acc[3][1] += a.w*w.y; acc[3][2] += a.w*w.z; acc[3][3] += a.w*w.w;
        }
        __syncthreads();
    }

    // ---- epilogue: z1 = relu(y0 + b0) ----
#pragma unroll
    for (int i = 0; i < 4; i++)
#pragma unroll
        for (int j = 0; j < 4; j++)
            sm.e.Z[m0 + i][n0 + j] = fmaxf(acc[i][j] + b0s[n0 + j], 0.f);
    // W1 transposed: W[c][n] = w1[n*64+c]
#pragma unroll
    for (int q = 0; q < 16; q++) {
        int idx = tid + q * 256;
        sm.e.W[idx & 63][idx >> 6] = w1[idx];
    }
    __syncthreads();

    float a2[4][4];
#pragma unroll
    for (int i = 0; i < 4; i++)
#pragma unroll
        for (int j = 0; j < 4; j++) a2[i][j] = b1s[n0 + j];
#pragma unroll 8
    for (int c = 0; c < 64; c++) {
        float zi0 = sm.e.Z[m0+0][c], zi1 = sm.e.Z[m0+1][c];
        float zi2 = sm.e.Z[m0+2][c], zi3 = sm.e.Z[m0+3][c];
        float4 wv = *(const float4*)&sm.e.W[c][n0];
        a2[0][0] += zi0*wv.x; a2[0][1] += zi0*wv.y; a2[0][2] += zi0*wv.z; a2[0][3] += zi0*wv.w;
        a2[1][0] += zi1*wv.x; a2[1][1] += zi1*wv.y; a2[1][2] += zi1*wv.z; a2[1][3] += zi1*wv.w;
        a2[2][0] += zi2*wv.x; a2[2][1] += zi2*wv.y; a2[2][2] += zi2*wv.z; a2[2][3] += zi2*wv.w;
        a2[3][0] += zi3*wv.x; a2[3][1] += zi3*wv.y; a2[3][2] += zi3*wv.z; a2[3][3] += zi3*wv.w;
    }
    __syncthreads();
    // overwrite Z with relu(z2)
#pragma unroll
    for (int i = 0; i < 4; i++)
#pragma unroll
        for (int j = 0; j < 4; j++)
            sm.e.Z[m0 + i][n0 + j] = fmaxf(a2[i][j], 0.f);
    // W2: W[o3][c]
#pragma unroll
    for (int q = 0; q < 4; q++) {
        int idx = tid + q * 256;
        sm.e.W[idx >> 6][idx & 63] = w2[idx];
    }
    __syncthreads();
    int o3 = tid & 15;
    int mb = tid >> 4;
#pragma unroll
    for (int g2 = 0; g2 < 4; g2++) {
        int m = mb + g2 * 16;
        float s = b2s[o3];
#pragma unroll 16
        for (int c = 0; c < 64; c++) s += sm.e.W[o3][c] * sm.e.Z[m][c];
        int t = t0 + m;
        if (t < L2) g_h2[(size_t)(b * L2 + t) * H2 + o3] = s;
    }
}

// ============================================================
// become_constant + signature depth2 (non-stream) + linear
// ============================================================
__global__ __launch_bounds__(256) void k_sig2(
    const int* __restrict__ lengths,
    const float* __restrict__ lw, const float* __restrict__ lb,
    float* __restrict__ out)
{
    __shared__ float hs[129][16];
    __shared__ float s2s[SIGC2];
    int b = blockIdx.x, tid = threadIdx.x;
    int adj = lengths[b] - 2 * KS + 2;
    if (adj < 1) adj = 1;
    if (adj > L2) adj = L2;
    int i = tid >> 4, j = tid & 15;
    float acc = 0.f;
    for (int c0 = 0; c0 < adj; c0 += 128) {
        for (int idx = tid; idx < 129 * 16; idx += 256) {
            int r = idx >> 4, c = idx & 15;
            int row = c0 - 1 + r;
            hs[r][c] = (row >= 0 && row < L2) ? g_h2[(size_t)(b * L2 + row) * H2 + c] : 0.f;
        }
        __syncthreads();
        int tend = min(c0 + 128, adj);
        for (int t = c0; t < tend; t++) {
            int r = t - c0 + 1;
            float hpi = hs[r-1][i], hpj = hs[r-1][j];
            float dxi = hs[r][i] - hpi, dxj = hs[r][j] - hpj;
            acc += hpi * dxj + 0.5f * dxi * dxj;
        }
        __syncthreads();
    }
    s2s[16 + tid] = acc;
    if (tid < 16) s2s[tid] = g_h2[(size_t)(b * L2 + adj - 1) * H2 + tid];
    __syncthreads();
    if (tid < OUTC) {
        float v = lb[tid];
        for (int c = 0; c < SIGC2; c++) v += lw[tid * SIGC2 + c] * s2s[c];
        out[b * OUTC + tid] = v;
    }
}

// ============================================================
extern "C" void kernel_launch(void* const* d_in, const int* in_sizes, int n_in,
                              void* d_out, int out_size) {
    const float* x      = (const float*)d_in[0];
    const int*   lens   = (const int*)  d_in[1];
    const float* a1_w0  = (const float*)d_in[2];
    const float* a1_b0  = (const float*)d_in[3];
    const float* a1_w1  = (const float*)d_in[4];
    const float* a1_b1  = (const float*)d_in[5];
    const float* a1_w2  = (const float*)d_in[6];
    const float* a1_b2  = (const float*)d_in[7];
    const float* a2_w0  = (const float*)d_in[8];
    const float* a2_b0  = (const float*)d_in[9];
    const float* a2_w1  = (const float*)d_in[10];
    const float* a2_b1  = (const float*)d_in[11];
    const float* a2_w2  = (const float*)d_in[12];
    const float* a2_b2  = (const float*)d_in[13];
    const float* lin_w  = (const float*)d_in[14];
    const float* lin_b  = (const float*)d_in[15];
    float* out = (float*)d_out;

    k_repack<<<512, 256>>>(a2_w0);
    k_aug1<<<dim3(8, B_), 128>>>(x, a1_w0, a1_b0, a1_w1, a1_b1, a1_w2, a1_b2);
    k_sig1_sum<<<dim3(NC1, B_), 512>>>();
    k_sig1_prefix<<<B_, 512>>>();
    k_sig1_write<<<dim3(NC1, B_), 512>>>();
    k_conv2<<<dim3(16, B_), 256>>>(a2_b0, a2_w1, a2_b1, a2_w2, a2_b2);
    k_sig2<<<B_, 256>>>(lens, lin_w, lin_b, out);
}

// round 3
// speedup vs baseline: 1.2066x; 1.2066x over previous
#include <cuda_runtime.h>
#include <cstdint>

#define B_    64
#define S_    1024
#define CIN   5
#define KS    4
#define H1    64
#define H2    16
#define OUTC  32
#define L1    1021          // S-K+1
#define C1    22            // H2+CIN+1
#define SIGC1 506
#define SC1P  512           // padded
#define L2    1018
#define SIGC2 272
#define NC1   16            // chunks for sig1 scan
#define CH1   64            // chunk length

// conv2 tiling
#define TM    128
#define SAS   130           // As row stride (floats), 8B-aligned, 4-way-store-conflict
#define SZ    66            // Z row stride
#define SW    68            // W row stride (16B aligned)
#define DSMF  (8448 + 64*SW)   // floats: max(As 8320 + Bs 4096, Z 8448 + W 4352) = 12800
#define DSMB  (DSMF * 4)       // 51200 bytes

// ---- scratch (device globals; no runtime allocation) ----
__device__ float g_h[B_ * L1 * C1];
__device__ float g_s1[(size_t)B_ * L1 * SC1P];
__device__ float g_wpad[KS * SC1P * H1];
__device__ float g_csum[B_ * NC1 * SC1P];
__device__ float g_h2[B_ * L2 * H2];

__device__ __forceinline__ unsigned long long ffma2(
    unsigned long long a, unsigned long long b, unsigned long long c) {
    unsigned long long d;
    asm("fma.rn.f32x2 %0, %1, %2, %3;" : "=l"(d) : "l"(a), "l"(b), "l"(c));
    return d;
}
__device__ __forceinline__ unsigned long long pack2(float v) {
    unsigned long long d;
    unsigned int r = __float_as_uint(v);
    asm("mov.b64 %0, {%1, %1};" : "=l"(d) : "r"(r));
    return d;
}
__device__ __forceinline__ void unpack2(unsigned long long p, float& lo, float& hi) {
    unsigned int a, b;
    asm("mov.b64 {%0, %1}, %2;" : "=r"(a), "=r"(b) : "l"(p));
    lo = __uint_as_float(a); hi = __uint_as_float(b);
}

// ============================================================
// Repack a2_w0 (O,C,K) -> wpad[k][c_pad][o]
// ============================================================
__global__ void k_repack(const float* __restrict__ w0) {
    int idx = blockIdx.x * blockDim.x + threadIdx.x;
    int o  = idx & 63;
    int c  = (idx >> 6) & (SC1P - 1);
    int kk = idx >> 15;
    float v = 0.f;
    if (c < SIGC1) v = w0[(o * SIGC1 + c) * KS + kk];
    g_wpad[idx] = v;
}

// ============================================================
// Augment 1
// ============================================================
__global__ __launch_bounds__(128) void k_aug1(
    const float* __restrict__ x,
    const float* __restrict__ w0, const float* __restrict__ b0,
    const float* __restrict__ w1, const float* __restrict__ b1,
    const float* __restrict__ w2, const float* __restrict__ b2)
{
    __shared__ float w0s[H1*CIN*KS], w1s[H1*H1], w2s[H2*H1];
    __shared__ float b0s[H1], b1s[H1], b2s[H2];
    int tid = threadIdx.x;
    for (int i = tid; i < H1*CIN*KS; i += 128) w0s[i] = w0[i];
    for (int i = tid; i < H1*H1;     i += 128) w1s[i] = w1[i];
    for (int i = tid; i < H2*H1;     i += 128) w2s[i] = w2[i];
    if (tid < H1) { b0s[tid] = b0[tid]; b1s[tid] = b1[tid]; }
    if (tid < H2) b2s[tid] = b2[tid];
    __syncthreads();

    int b = blockIdx.y;
    int t = blockIdx.x * 128 + tid;
    if (t >= L1) return;

    float xr[KS][CIN];
#pragma unroll
    for (int k = 0; k < KS; k++)
#pragma unroll
        for (int c = 0; c < CIN; c++)
            xr[k][c] = x[((size_t)(b * S_) + t + k) * CIN + c];

    float z1[H1];
#pragma unroll
    for (int o = 0; o < H1; o++) {
        float s = b0s[o];
#pragma unroll
        for (int c = 0; c < CIN; c++)
#pragma unroll
            for (int k = 0; k < KS; k++)
                s += w0s[(o*CIN + c)*KS + k] * xr[k][c];
        z1[o] = fmaxf(s, 0.f);
    }
    float z3[H2];
#pragma unroll
    for (int o = 0; o < H2; o++) z3[o] = b2s[o];
    for (int o2 = 0; o2 < H1; o2++) {
        float s = b1s[o2];
#pragma unroll
        for (int c = 0; c < H1; c++) s += w1s[o2*H1 + c] * z1[c];
        s = fmaxf(s, 0.f);
#pragma unroll
        for (int o = 0; o < H2; o++) z3[o] += w2s[o*H1 + o2] * s;
    }
    float* hrow = &g_h[(size_t)(b * L1 + t) * C1];
#pragma unroll
    for (int c = 0; c < CIN; c++) hrow[c] = xr[KS-1][c];
    hrow[CIN] = (float)t * (1.0f / (float)(L1 - 1));
#pragma unroll
    for (int o = 0; o < H2; o++) hrow[CIN + 1 + o] = z3[o];
}

// ============================================================
// Sig1 pass A
// ============================================================
__global__ __launch_bounds__(512) void k_sig1_sum() {
    __shared__ float hs[CH1 + 1][C1];
    int b = blockIdx.y, nc = blockIdx.x, tid = threadIdx.x;
    int c0 = nc * CH1;
    for (int idx = tid; idx < (CH1 + 1) * C1; idx += 512) {
        int r = idx / C1, c = idx - r * C1;
        int row = c0 - 1 + r;
        hs[r][c] = (row >= 0 && row < L1) ? g_h[(size_t)(b * L1 + row) * C1 + c] : 0.f;
    }
    __syncthreads();
    if (tid >= C1 * C1) return;
    int i = tid / C1, j = tid - i * C1;
    float acc = 0.f;
    int tend = min(c0 + CH1, L1);
    for (int t = c0; t < tend; t++) {
        int r = t - c0 + 1;
        float hpi = hs[r-1][i], hpj = hs[r-1][j];
        float dxi = hs[r][i] - hpi, dxj = hs[r][j] - hpj;
        acc += hpi * dxj + 0.5f * dxi * dxj;
    }
    g_csum[(b * NC1 + nc) * SC1P + tid] = acc;
}

__global__ void k_sig1_prefix() {
    int b = blockIdx.x, tid = threadIdx.x;
    if (tid >= C1 * C1) return;
    float run = 0.f;
    for (int nc = 0; nc < NC1; nc++) {
        int idx = (b * NC1 + nc) * SC1P + tid;
        float v = g_csum[idx];
        g_csum[idx] = run;
        run += v;
    }
}

__global__ __launch_bounds__(512) void k_sig1_write() {
    __shared__ float hs[CH1 + 1][C1];
    int b = blockIdx.y, nc = blockIdx.x, tid = threadIdx.x;
    int c0 = nc * CH1;
    for (int idx = tid; idx < (CH1 + 1) * C1; idx += 512) {
        int r = idx / C1, c = idx - r * C1;
        int row = c0 - 1 + r;
        hs[r][c] = (row >= 0 && row < L1) ? g_h[(size_t)(b * L1 + row) * C1 + c] : 0.f;
    }
    __syncthreads();
    int tend = min(c0 + CH1, L1);
    if (tid < C1 * C1) {
        int i = tid / C1, j = tid - i * C1;
        float acc = g_csum[(b * NC1 + nc) * SC1P + tid];
        for (int t = c0; t < tend; t++) {
            int r = t - c0 + 1;
            float hpi = hs[r-1][i], hpj = hs[r-1][j];
            float dxi = hs[r][i] - hpi, dxj = hs[r][j] - hpj;
            acc += hpi * dxj + 0.5f * dxi * dxj;
            g_s1[((size_t)(b * L1 + t)) * SC1P + C1 + tid] = acc;
        }
    } else {
        int c = tid - C1 * C1;
        int ch = (c < C1) ? c : (C1 * C1 + c);
        for (int t = c0; t < tend; t++) {
            int r = t - c0 + 1;
            float v = (c < C1) ? hs[r][c] : 0.f;
            g_s1[((size_t)(b * L1 + t)) * SC1P + ch] = v;
        }
    }
}

// ============================================================
// Conv stack 2: 128x64 tile GEMM (K=2048) with FFMA2 + fused epilogue
// Thread micro-tile 8m x 4n; acc packed as (m, m+1) pairs.
// ============================================================
__global__ __launch_bounds__(256, 4) void k_conv2(
    const float* __restrict__ b0,
    const float* __restrict__ w1, const float* __restrict__ b1,
    const float* __restrict__ w2, const float* __restrict__ b2)
{
    extern __shared__ float dsm[];
    float* As = dsm;               // [64][SAS] c-major, m contiguous
    float* Bs = dsm + 64 * SAS;    // [64][64]
    float* Z  = dsm;               // [128][SZ]
    float* Wm = dsm + 128 * SZ;    // [64][SW]
    __shared__ float b0s[64], b1s[64], b2s[16];

    int tid = threadIdx.x;
    int b = blockIdx.y, t0 = blockIdx.x * TM;
    if (tid < 64) { b0s[tid] = b0[tid]; b1s[tid] = b1[tid]; }
    if (tid < 16) b2s[tid] = b2[tid];

    int tx = tid & 15, ty = tid >> 4;
    int m0 = ty * 8, n0 = tx * 4;

    unsigned long long acc2[4][4];
#pragma unroll
    for (int p = 0; p < 4; p++)
#pragma unroll
        for (int j = 0; j < 4; j++) acc2[p][j] = 0ULL;

    const float* pAbase = g_s1 + (size_t)b * L1 * SC1P;
    for (int kb = 0; kb < 32; kb++) {
        int kk = kb >> 3;
        int cb = (kb & 7) << 6;
        // A tile: 128 rows x 64 ch, transpose to As[c][m]
#pragma unroll
        for (int q = 0; q < 8; q++) {
            int idx = tid + q * 256;
            int m = idx >> 4, c4 = idx & 15;
            int row = t0 + kk + m;
            float4 v = make_float4(0.f, 0.f, 0.f, 0.f);
            if (row < L1)
                v = *(const float4*)&pAbase[(size_t)row * SC1P + cb + c4 * 4];
            As[(c4*4+0)*SAS + m] = v.x;
            As[(c4*4+1)*SAS + m] = v.y;
            As[(c4*4+2)*SAS + m] = v.z;
            As[(c4*4+3)*SAS + m] = v.w;
        }
        const float4* pB = (const float4*)(g_wpad + (kk * SC1P + cb) * 64);
#pragma unroll
        for (int q = 0; q < 4; q++)
            ((float4*)Bs)[tid + q * 256] = pB[tid + q * 256];
        __syncthreads();
#pragma unroll
        for (int k = 0; k < 64; k++) {
            float4 wv = *(const float4*)&Bs[k * 64 + n0];
            unsigned long long wp0 = pack2(wv.x), wp1 = pack2(wv.y);
            unsigned long long wp2 = pack2(wv.z), wp3 = pack2(wv.w);
            const unsigned long long* pa = (const unsigned long long*)&As[k * SAS + m0];
            unsigned long long a0 = pa[0], a1 = pa[1], a2v = pa[2], a3 = pa[3];
            acc2[0][0] = ffma2(a0, wp0, acc2[0][0]);
            acc2[0][1] = ffma2(a0, wp1, acc2[0][1]);
            acc2[0][2] = ffma2(a0, wp2, acc2[0][2]);
            acc2[0][3] = ffma2(a0, wp3, acc2[0][3]);
            acc2[1][0] = ffma2(a1, wp0, acc2[1][0]);
            acc2[1][1] = ffma2(a1, wp1, acc2[1][1]);
            acc2[1][2] = ffma2(a1, wp2, acc2[1][2]);
            acc2[1][3] = ffma2(a1, wp3, acc2[1][3]);
            acc2[2][0] = ffma2(a2v, wp0, acc2[2][0]);
            acc2[2][1] = ffma2(a2v, wp1, acc2[2][1]);
            acc2[2][2] = ffma2(a2v, wp2, acc2[2][2]);
            acc2[2][3] = ffma2(a2v, wp3, acc2[2][3]);
            acc2[3][0] = ffma2(a3, wp0, acc2[3][0]);
            acc2[3][1] = ffma2(a3, wp1, acc2[3][1]);
            acc2[3][2] = ffma2(a3, wp2, acc2[3][2]);
            acc2[3][3] = ffma2(a3, wp3, acc2[3][3]);
        }
        __syncthreads();
    }

    // ---- epilogue: Z = relu(y0 + b0) ----
#pragma unroll
    for (int p = 0; p < 4; p++)
#pragma unroll
        for (int j = 0; j < 4; j++) {
            float lo, hi;
            unpack2(acc2[p][j], lo, hi);
            Z[(m0 + 2*p    ) * SZ + n0 + j] = fmaxf(lo + b0s[n0 + j], 0.f);
            Z[(m0 + 2*p + 1) * SZ + n0 + j] = fmaxf(hi + b0s[n0 + j], 0.f);
        }
    // W1 transposed: Wm[c][n] = w1[n*64+c]
#pragma unroll
    for (int q = 0; q < 16; q++) {
        int idx = tid + q * 256;
        Wm[(idx & 63) * SW + (idx >> 6)] = w1[idx];
    }
    __syncthreads();

    float a2[8][4];
#pragma unroll
    for (int i = 0; i < 8; i++)
#pragma unroll
        for (int j = 0; j < 4; j++) a2[i][j] = b1s[n0 + j];
#pragma unroll 4
    for (int c = 0; c < 64; c++) {
        float4 wv = *(const float4*)&Wm[c * SW + n0];
#pragma unroll
        for (int i = 0; i < 8; i++) {
            float zi = Z[(m0 + i) * SZ + c];
            a2[i][0] += zi * wv.x; a2[i][1] += zi * wv.y;
            a2[i][2] += zi * wv.z; a2[i][3] += zi * wv.w;
        }
    }
    __syncthreads();
#pragma unroll
    for (int i = 0; i < 8; i++)
#pragma unroll
        for (int j = 0; j < 4; j++)
            Z[(m0 + i) * SZ + n0 + j] = fmaxf(a2[i][j], 0.f);
    // W2: Wm[o3][c]
#pragma unroll
    for (int q = 0; q < 4; q++) {
        int idx = tid + q * 256;
        Wm[(idx >> 6) * SW + (idx & 63)] = w2[idx];
    }
    __syncthreads();
    int o3 = tid & 15;
    int mb = tid >> 4;
#pragma unroll
    for (int g2 = 0; g2 < 8; g2++) {
        int m = mb + g2 * 16;
        float s = b2s[o3];
#pragma unroll 16
        for (int c = 0; c < 64; c++) s += Wm[o3 * SW + c] * Z[m * SZ + c];
        int t = t0 + m;
        if (t < L2) g_h2[(size_t)(b * L2 + t) * H2 + o3] = s;
    }
}

// ============================================================
// become_constant + signature depth2 (non-stream) + linear
// ============================================================
__global__ __launch_bounds__(256) void k_sig2(
    const int* __restrict__ lengths,
    const float* __restrict__ lw, const float* __restrict__ lb,
    float* __restrict__ out)
{
    __shared__ float hs[129][16];
    __shared__ float s2s[SIGC2];
    int b = blockIdx.x, tid = threadIdx.x;
    int adj = lengths[b] - 2 * KS + 2;
    if (adj < 1) adj = 1;
    if (adj > L2) adj = L2;
    int i = tid >> 4, j = tid & 15;
    float acc = 0.f;
    for (int c0 = 0; c0 < adj; c0 += 128) {
        for (int idx = tid; idx < 129 * 16; idx += 256) {
            int r = idx >> 4, c = idx & 15;
            int row = c0 - 1 + r;
            hs[r][c] = (row >= 0 && row < L2) ? g_h2[(size_t)(b * L2 + row) * H2 + c] : 0.f;
        }
        __syncthreads();
        int tend = min(c0 + 128, adj);
        for (int t = c0; t < tend; t++) {
            int r = t - c0 + 1;
            float hpi = hs[r-1][i], hpj = hs[r-1][j];
            float dxi = hs[r][i] - hpi, dxj = hs[r][j] - hpj;
            acc += hpi * dxj + 0.5f * dxi * dxj;
        }
        __syncthreads();
    }
    s2s[16 + tid] = acc;
    if (tid < 16) s2s[tid] = g_h2[(size_t)(b * L2 + adj - 1) * H2 + tid];
    __syncthreads();
    if (tid < OUTC) {
        float v = lb[tid];
        for (int c = 0; c < SIGC2; c++) v += lw[tid * SIGC2 + c] * s2s[c];
        out[b * OUTC + tid] = v;
    }
}

// ============================================================
extern "C" void kernel_launch(void* const* d_in, const int* in_sizes, int n_in,
                              void* d_out, int out_size) {
    const float* x      = (const float*)d_in[0];
    const int*   lens   = (const int*)  d_in[1];
    const float* a1_w0  = (const float*)d_in[2];
    const float* a1_b0  = (const float*)d_in[3];
    const float* a1_w1  = (const float*)d_in[4];
    const float* a1_b1  = (const float*)d_in[5];
    const float* a1_w2  = (const float*)d_in[6];
    const float* a1_b2  = (const float*)d_in[7];
    const float* a2_w0  = (const float*)d_in[8];
    const float* a2_b0  = (const float*)d_in[9];
    const float* a2_w1  = (const float*)d_in[10];
    const float* a2_b1  = (const float*)d_in[11];
    const float* a2_w2  = (const float*)d_in[12];
    const float* a2_b2  = (const float*)d_in[13];
    const float* lin_w  = (const float*)d_in[14];
    const float* lin_b  = (const float*)d_in[15];
    float* out = (float*)d_out;

    static bool attr_set = false;
    if (!attr_set) {
        cudaFuncSetAttribute(k_conv2, cudaFuncAttributeMaxDynamicSharedMemorySize, DSMB);
        attr_set = true;
    }

    k_repack<<<512, 256>>>(a2_w0);
    k_aug1<<<dim3(8, B_), 128>>>(x, a1_w0, a1_b0, a1_w1, a1_b1, a1_w2, a1_b2);
    k_sig1_sum<<<dim3(NC1, B_), 512>>>();
    k_sig1_prefix<<<B_, 512>>>();
    k_sig1_write<<<dim3(NC1, B_), 512>>>();
    k_conv2<<<dim3(8, B_), 256, DSMB>>>(a2_b0, a2_w1, a2_b1, a2_w2, a2_b2);
    k_sig2<<<B_, 256>>>(lens, lin_w, lin_b, out);
}